// round 4
// baseline (speedup 1.0000x reference)
#include <cuda_runtime.h>

#define N_NODES 50000
#define N_EDGES 800000
#define IN_F    64
#define OUT_F   32
#define N_STEPS 20
#define LR      0.1f
#define SLOPE   0.2f
#define FULLMASK 0xFFFFFFFFu
#define NEG_INF  __int_as_float(0xFF800000)

#define SCAN_TPB 1024
#define SCAN_BLOCKS ((N_NODES + SCAN_TPB - 1) / SCAN_TPB)   // 49
#define MAX_CACHE 8   // register-cached edge blocks per warp -> deg <= 256

// ---------------- scratch (device globals; no allocation allowed) ----------------
__device__ float g_transformed[N_NODES * OUT_F];
__device__ float g_mu[N_NODES * OUT_F];
__device__ float g_es[2 * N_NODES];   // double-buffered (parity)
__device__ float g_ed[2 * N_NODES];
__device__ int   g_degi[N_NODES];
__device__ int   g_rowstart[N_NODES + 1];
__device__ int   g_fill[N_NODES];
__device__ int   g_bsum[SCAN_BLOCKS];
__device__ int   g_boff[SCAN_BLOCKS];
__device__ int   g_csr_src[N_EDGES];
__device__ int   g_csr_eid[N_EDGES];

// ---------------- setup kernels ----------------

__global__ void init_kernel() {
    int i = blockIdx.x * blockDim.x + threadIdx.x;
    if (i < N_NODES) g_degi[i] = 0;
}

// transformed = mu_upper @ W^T. Warp per node (grid-stride), lane = out feature.
// Wt transposed in shared (conflict-free); mu_upper row broadcast via shfl.
__global__ void gemm_kernel(const float* __restrict__ mu_upper,
                            const float* __restrict__ W) {
    __shared__ float Wt[IN_F][OUT_F];   // Wt[k][f] = W[f*IN_F + k]
    for (int i = threadIdx.x; i < IN_F * OUT_F; i += blockDim.x) {
        int k = i >> 5, f = i & 31;
        Wt[k][f] = W[f * IN_F + k];
    }
    __syncthreads();

    int lane = threadIdx.x & 31;
    int warpsPerGrid = (gridDim.x * blockDim.x) >> 5;
    int w0 = (blockIdx.x * blockDim.x + threadIdx.x) >> 5;

    for (int n = w0; n < N_NODES; n += warpsPerGrid) {
        const float* row = mu_upper + n * IN_F;
        float r0 = row[lane];
        float r1 = row[lane + 32];
        float acc = 0.0f;
#pragma unroll
        for (int k = 0; k < 32; ++k)
            acc = fmaf(__shfl_sync(FULLMASK, r0, k), Wt[k][lane], acc);
#pragma unroll
        for (int k = 0; k < 32; ++k)
            acc = fmaf(__shfl_sync(FULLMASK, r1, k), Wt[32 + k][lane], acc);
        g_transformed[n * OUT_F + lane] = acc;
    }
}

__global__ void count_kernel(const int* __restrict__ dst) {
    int e = blockIdx.x * blockDim.x + threadIdx.x;
    if (e >= N_EDGES) return;
    atomicAdd(&g_degi[dst[e]], 1);
}

// scan phase A: per-block exclusive scan; block totals to g_bsum
__global__ void scanA_kernel() {
    __shared__ int warp_sums[32];
    int tid  = threadIdx.x;
    int lane = tid & 31;
    int wid  = tid >> 5;
    int idx  = blockIdx.x * SCAN_TPB + tid;

    int v = (idx < N_NODES) ? g_degi[idx] : 0;
    int x = v;
#pragma unroll
    for (int off = 1; off < 32; off <<= 1) {
        int y = __shfl_up_sync(FULLMASK, x, off);
        if (lane >= off) x += y;
    }
    if (lane == 31) warp_sums[wid] = x;
    __syncthreads();
    if (wid == 0) {
        int w = warp_sums[lane];
#pragma unroll
        for (int off = 1; off < 32; off <<= 1) {
            int y = __shfl_up_sync(FULLMASK, w, off);
            if (lane >= off) w += y;
        }
        warp_sums[lane] = w;
    }
    __syncthreads();
    int incl = x + ((wid > 0) ? warp_sums[wid - 1] : 0);
    if (idx < N_NODES) g_rowstart[idx] = incl - v;   // exclusive within block
    if (tid == SCAN_TPB - 1) g_bsum[blockIdx.x] = incl;
}

// scan phase B: exclusive scan of block sums (64-thread Hillis-Steele)
__global__ void scanB_kernel() {
    __shared__ int s[64];
    int t = threadIdx.x;
    int v = (t < SCAN_BLOCKS) ? g_bsum[t] : 0;
    s[t] = v;
    __syncthreads();
#pragma unroll
    for (int off = 1; off < 64; off <<= 1) {
        int x = (t >= off) ? s[t - off] : 0;
        __syncthreads();
        s[t] += x;
        __syncthreads();
    }
    if (t < SCAN_BLOCKS) g_boff[t] = s[t] - v;
    if (t == 63) g_rowstart[N_NODES] = s[63];
}

// scan phase C: add block offsets, init fill cursors
__global__ void scanC_kernel() {
    int idx = blockIdx.x * blockDim.x + threadIdx.x;
    if (idx >= N_NODES) return;
    int r = g_rowstart[idx] + g_boff[idx >> 10];
    g_rowstart[idx] = r;
    g_fill[idx] = r;
}

__global__ void scatter_kernel(const int* __restrict__ src,
                               const int* __restrict__ dst) {
    int e = blockIdx.x * blockDim.x + threadIdx.x;
    if (e >= N_EDGES) return;
    int pos = atomicAdd(&g_fill[dst[e]], 1);
    g_csr_src[pos] = src[e];
    g_csr_eid[pos] = e;
}

// ---------------- step 0: uniform-alpha top-down + node update (mu0 = 0) ----------------
__global__ void step0_kernel(const float* __restrict__ a_vec) {
    int t = blockIdx.x * blockDim.x + threadIdx.x;
    int n = t >> 5;
    int lane = t & 31;
    if (n >= N_NODES) return;

    int beg = g_rowstart[n], end = g_rowstart[n + 1];
    float acc = 0.0f;
    for (int base = beg; base < end; base += 32) {
        int i = base + lane;
        int s = (i < end) ? g_csr_src[i] : 0;
        int cnt = min(32, end - base);
        for (int j = 0; j < cnt; ++j) {
            int sj = __shfl_sync(FULLMASK, s, j);
            acc += __ldg(&g_transformed[sj * OUT_F + lane]);
        }
    }
    float inv = 1.0f / ((float)(end - beg) + 1e-8f);
    float mh = fmaxf(acc * inv, 0.0f);   // mu_hat
    float er = -mh;                      // mu0 = 0

    float ps = er * a_vec[lane];
    float pd = er * a_vec[OUT_F + lane];
#pragma unroll
    for (int off = 16; off > 0; off >>= 1) {
        ps += __shfl_xor_sync(FULLMASK, ps, off);
        pd += __shfl_xor_sync(FULLMASK, pd, off);
    }
    if (lane == 0) {
        g_es[n] = ps;            // parity buffer 0
        g_ed[n] = pd;
    }
    g_mu[n * OUT_F + lane] = LR * mh;    // mu1 = mu0 - LR*err
}

// ---------------- fused step: softmax + aggregate + node update ----------------
// mode 0: intermediate step (writes mu, es/ed[out_par])
// mode 1: final (writes out_mu/out_err/out_alpha)
__global__ void fused_step_kernel(const float* __restrict__ a_vec,
                                  int in_par, int out_par, int mode,
                                  float* __restrict__ out_mu,
                                  float* __restrict__ out_err,
                                  float* __restrict__ out_alpha) {
    int t = blockIdx.x * blockDim.x + threadIdx.x;
    int n = t >> 5;
    int lane = t & 31;
    if (n >= N_NODES) return;

    const float* es_in = g_es + in_par * N_NODES;
    const float* ed_in = g_ed + in_par * N_NODES;

    int beg = g_rowstart[n], end = g_rowstart[n + 1];
    int deg = end - beg;
    float ed_n = ed_in[n];

    float mx = NEG_INF, sm = 0.0f, acc = 0.0f, inv;

    if (deg <= 32 * MAX_CACHE) {
        // -------- register-cached path --------
        float sc_c[MAX_CACHE];
        int   s_c[MAX_CACHE];
        int nblk = (deg + 31) >> 5;
#pragma unroll
        for (int c = 0; c < MAX_CACHE; ++c) {
            int i = beg + c * 32 + lane;
            float sc = NEG_INF;
            int s = 0;
            if (c < nblk && i < end) {
                s = g_csr_src[i];
                sc = es_in[s] + ed_n;
                sc = (sc > 0.0f) ? sc : SLOPE * sc;
            }
            sc_c[c] = sc;
            s_c[c]  = s;
            mx = fmaxf(mx, sc);
        }
#pragma unroll
        for (int off = 16; off > 0; off >>= 1)
            mx = fmaxf(mx, __shfl_xor_sync(FULLMASK, mx, off));

#pragma unroll
        for (int c = 0; c < MAX_CACHE; ++c) {
            if (c >= nblk) break;
            float ev = __expf(sc_c[c] - mx);   // inactive lanes: exp(-inf)=0
            sm += ev;
            int cnt = min(32, deg - c * 32);
            for (int j = 0; j < cnt; ++j) {
                float evj = __shfl_sync(FULLMASK, ev, j);
                int   sj  = __shfl_sync(FULLMASK, s_c[c], j);
                acc += evj * __ldg(&g_transformed[sj * OUT_F + lane]);
            }
        }
#pragma unroll
        for (int off = 16; off > 0; off >>= 1)
            sm += __shfl_xor_sync(FULLMASK, sm, off);
        inv = 1.0f / (sm + 1e-8f);

        if (mode == 1) {
#pragma unroll
            for (int c = 0; c < MAX_CACHE; ++c) {
                if (c >= nblk) break;
                int i = beg + c * 32 + lane;
                if (i < end)
                    out_alpha[g_csr_eid[i]] = __expf(sc_c[c] - mx) * inv;
            }
        }
    } else {
        // -------- fallback (deg > 256): re-read path --------
        for (int i = beg + lane; i < end; i += 32) {
            int s = g_csr_src[i];
            float sc = es_in[s] + ed_n;
            sc = (sc > 0.0f) ? sc : SLOPE * sc;
            mx = fmaxf(mx, sc);
        }
#pragma unroll
        for (int off = 16; off > 0; off >>= 1)
            mx = fmaxf(mx, __shfl_xor_sync(FULLMASK, mx, off));

        for (int base = beg; base < end; base += 32) {
            int i = base + lane;
            int s = 0;
            float ev = 0.0f;
            if (i < end) {
                s = g_csr_src[i];
                float sc = es_in[s] + ed_n;
                sc = (sc > 0.0f) ? sc : SLOPE * sc;
                ev = __expf(sc - mx);
                sm += ev;
            }
            int cnt = min(32, end - base);
            for (int j = 0; j < cnt; ++j) {
                float evj = __shfl_sync(FULLMASK, ev, j);
                int   sj  = __shfl_sync(FULLMASK, s, j);
                acc += evj * __ldg(&g_transformed[sj * OUT_F + lane]);
            }
        }
#pragma unroll
        for (int off = 16; off > 0; off >>= 1)
            sm += __shfl_xor_sync(FULLMASK, sm, off);
        inv = 1.0f / (sm + 1e-8f);

        if (mode == 1) {
            for (int i = beg + lane; i < end; i += 32) {
                int s = g_csr_src[i];
                float sc = es_in[s] + ed_n;
                sc = (sc > 0.0f) ? sc : SLOPE * sc;
                out_alpha[g_csr_eid[i]] = __expf(sc - mx) * inv;
            }
        }
    }

    // -------- fused node update (warp-local: only needs agg[n]) --------
    int idx = n * OUT_F + lane;
    float mh = fmaxf(acc * inv, 0.0f);
    float mu = g_mu[idx];
    float er = mu - mh;

    if (mode == 0) {
        float ps = er * a_vec[lane];
        float pd = er * a_vec[OUT_F + lane];
#pragma unroll
        for (int off = 16; off > 0; off >>= 1) {
            ps += __shfl_xor_sync(FULLMASK, ps, off);
            pd += __shfl_xor_sync(FULLMASK, pd, off);
        }
        if (lane == 0) {
            g_es[out_par * N_NODES + n] = ps;
            g_ed[out_par * N_NODES + n] = pd;
        }
        g_mu[idx] = mu - LR * er;
    } else {
        out_mu[idx]  = mu;
        out_err[idx] = er;
    }
}

// ---------------- launch ----------------
extern "C" void kernel_launch(void* const* d_in, const int* in_sizes, int n_in,
                              void* d_out, int out_size) {
    const float* mu_upper   = (const float*)d_in[0];
    const float* W          = (const float*)d_in[1];
    const float* a_vec      = (const float*)d_in[2];
    const int*   edge_index = (const int*)d_in[3];
    const int*   src = edge_index;
    const int*   dst = edge_index + N_EDGES;

    float* out       = (float*)d_out;
    float* out_mu    = out;
    float* out_err   = out + N_NODES * OUT_F;
    float* out_alpha = out + 2 * N_NODES * OUT_F;

    const int TPB = 256;
    const int nodeBlocks1 = (N_NODES + TPB - 1) / TPB;
    const int edgeBlocks  = (N_EDGES + TPB - 1) / TPB;
    const int warpNodeBlocks = (N_NODES * 32 + TPB - 1) / TPB;

    init_kernel<<<nodeBlocks1, TPB>>>();
    gemm_kernel<<<1024, TPB>>>(mu_upper, W);
    count_kernel<<<edgeBlocks, TPB>>>(dst);
    scanA_kernel<<<SCAN_BLOCKS, SCAN_TPB>>>();
    scanB_kernel<<<1, 64>>>();
    scanC_kernel<<<nodeBlocks1, TPB>>>();
    scatter_kernel<<<edgeBlocks, TPB>>>(src, dst);

    // step 1 (uniform alpha0) -> es/ed parity 0, mu updated
    step0_kernel<<<warpNodeBlocks, TPB>>>(a_vec);

    // steps 2..20
    for (int t = 1; t < N_STEPS; ++t) {
        fused_step_kernel<<<warpNodeBlocks, TPB>>>(
            a_vec, (t - 1) & 1, t & 1, 0, nullptr, nullptr, nullptr);
    }
    // final top-down with alpha_20 -> outputs
    fused_step_kernel<<<warpNodeBlocks, TPB>>>(
        a_vec, (N_STEPS - 1) & 1, 0, 1, out_mu, out_err, out_alpha);
}

// round 5
// speedup vs baseline: 1.2082x; 1.2082x over previous
#include <cuda_runtime.h>

#define N_NODES 50000
#define N_EDGES 800000
#define IN_F    64
#define OUT_F   32
#define N_STEPS 20
#define LR      0.1f
#define SLOPE   0.2f
#define FULLMASK 0xFFFFFFFFu
#define NEG_INF  __int_as_float(0xFF800000)

#define SCAN_TPB 1024
#define SCAN_BLOCKS ((N_NODES + SCAN_TPB - 1) / SCAN_TPB)   // 49

// ---------------- scratch (device globals; no allocation allowed) ----------------
__device__ float g_transformed[N_NODES * OUT_F];
__device__ float g_mu[N_NODES * OUT_F];
__device__ float g_es[2 * N_NODES];   // double-buffered (parity)
__device__ float g_ed[2 * N_NODES];
__device__ int   g_degi[N_NODES];
__device__ int   g_rowstart[N_NODES + 1];
__device__ int   g_fill[N_NODES];
__device__ int   g_bsum[SCAN_BLOCKS];
__device__ int   g_boff[SCAN_BLOCKS];
__device__ int   g_csr_src[N_EDGES];
__device__ int   g_csr_eid[N_EDGES];

__device__ __forceinline__ float leaky(float x) {
    return (x > 0.0f) ? x : SLOPE * x;
}

// ---------------- setup kernels ----------------

__global__ void init_kernel() {
    int i = blockIdx.x * blockDim.x + threadIdx.x;
    if (i < N_NODES) g_degi[i] = 0;
}

// transformed = mu_upper @ W^T. Warp per node (grid-stride), lane = out feature.
__global__ void gemm_kernel(const float* __restrict__ mu_upper,
                            const float* __restrict__ W) {
    __shared__ float Wt[IN_F][OUT_F];   // Wt[k][f] = W[f*IN_F + k]
    for (int i = threadIdx.x; i < IN_F * OUT_F; i += blockDim.x) {
        int k = i >> 5, f = i & 31;
        Wt[k][f] = W[f * IN_F + k];
    }
    __syncthreads();

    int lane = threadIdx.x & 31;
    int warpsPerGrid = (gridDim.x * blockDim.x) >> 5;
    int w0 = (blockIdx.x * blockDim.x + threadIdx.x) >> 5;

    for (int n = w0; n < N_NODES; n += warpsPerGrid) {
        const float* row = mu_upper + n * IN_F;
        float r0 = row[lane];
        float r1 = row[lane + 32];
        float acc = 0.0f;
#pragma unroll
        for (int k = 0; k < 32; ++k)
            acc = fmaf(__shfl_sync(FULLMASK, r0, k), Wt[k][lane], acc);
#pragma unroll
        for (int k = 0; k < 32; ++k)
            acc = fmaf(__shfl_sync(FULLMASK, r1, k), Wt[32 + k][lane], acc);
        g_transformed[n * OUT_F + lane] = acc;
    }
}

__global__ void count_kernel(const int* __restrict__ dst) {
    int e = blockIdx.x * blockDim.x + threadIdx.x;
    if (e >= N_EDGES) return;
    atomicAdd(&g_degi[dst[e]], 1);
}

// scan phase A: per-block exclusive scan; block totals to g_bsum
__global__ void scanA_kernel() {
    __shared__ int warp_sums[32];
    int tid  = threadIdx.x;
    int lane = tid & 31;
    int wid  = tid >> 5;
    int idx  = blockIdx.x * SCAN_TPB + tid;

    int v = (idx < N_NODES) ? g_degi[idx] : 0;
    int x = v;
#pragma unroll
    for (int off = 1; off < 32; off <<= 1) {
        int y = __shfl_up_sync(FULLMASK, x, off);
        if (lane >= off) x += y;
    }
    if (lane == 31) warp_sums[wid] = x;
    __syncthreads();
    if (wid == 0) {
        int w = warp_sums[lane];
#pragma unroll
        for (int off = 1; off < 32; off <<= 1) {
            int y = __shfl_up_sync(FULLMASK, w, off);
            if (lane >= off) w += y;
        }
        warp_sums[lane] = w;
    }
    __syncthreads();
    int incl = x + ((wid > 0) ? warp_sums[wid - 1] : 0);
    if (idx < N_NODES) g_rowstart[idx] = incl - v;
    if (tid == SCAN_TPB - 1) g_bsum[blockIdx.x] = incl;
}

// scan phase B: exclusive scan of block sums
__global__ void scanB_kernel() {
    __shared__ int s[64];
    int t = threadIdx.x;
    int v = (t < SCAN_BLOCKS) ? g_bsum[t] : 0;
    s[t] = v;
    __syncthreads();
#pragma unroll
    for (int off = 1; off < 64; off <<= 1) {
        int x = (t >= off) ? s[t - off] : 0;
        __syncthreads();
        s[t] += x;
        __syncthreads();
    }
    if (t < SCAN_BLOCKS) g_boff[t] = s[t] - v;
    if (t == 63) g_rowstart[N_NODES] = s[63];
}

// scan phase C: add block offsets, init fill cursors
__global__ void scanC_kernel() {
    int idx = blockIdx.x * blockDim.x + threadIdx.x;
    if (idx >= N_NODES) return;
    int r = g_rowstart[idx] + g_boff[idx >> 10];
    g_rowstart[idx] = r;
    g_fill[idx] = r;
}

__global__ void scatter_kernel(const int* __restrict__ src,
                               const int* __restrict__ dst) {
    int e = blockIdx.x * blockDim.x + threadIdx.x;
    if (e >= N_EDGES) return;
    int pos = atomicAdd(&g_fill[dst[e]], 1);
    g_csr_src[pos] = src[e];
    g_csr_eid[pos] = e;
}

// ---------------- step 0: uniform-alpha top-down + node update (mu0 = 0) ----------------
__global__ void step0_kernel(const float* __restrict__ a_vec) {
    int t = blockIdx.x * blockDim.x + threadIdx.x;
    int n = t >> 5;
    int lane = t & 31;
    if (n >= N_NODES) return;

    int beg = g_rowstart[n], end = g_rowstart[n + 1];
    float acc = 0.0f;
    for (int base = beg; base < end; base += 32) {
        int i = base + lane;
        int s = (i < end) ? g_csr_src[i] : 0;
        int cnt = min(32, end - base);
#pragma unroll 8
        for (int j = 0; j < cnt; ++j) {
            int sj = __shfl_sync(FULLMASK, s, j);
            acc += __ldg(&g_transformed[sj * OUT_F + lane]);
        }
    }
    float inv = 1.0f / ((float)(end - beg) + 1e-8f);
    float mh = fmaxf(acc * inv, 0.0f);
    float er = -mh;                      // mu0 = 0

    float ps = er * a_vec[lane];
    float pd = er * a_vec[OUT_F + lane];
#pragma unroll
    for (int off = 16; off > 0; off >>= 1) {
        ps += __shfl_xor_sync(FULLMASK, ps, off);
        pd += __shfl_xor_sync(FULLMASK, pd, off);
    }
    if (lane == 0) {
        g_es[n] = ps;
        g_ed[n] = pd;
    }
    g_mu[n * OUT_F + lane] = LR * mh;    // mu1
}

// ---------------- fused step: softmax + aggregate + node update ----------------
// mode 0: intermediate (writes mu, es/ed[out_par]); mode 1: final outputs.
__global__ void fused_step_kernel(const float* __restrict__ a_vec,
                                  int in_par, int out_par, int mode,
                                  float* __restrict__ out_mu,
                                  float* __restrict__ out_err,
                                  float* __restrict__ out_alpha) {
    int t = blockIdx.x * blockDim.x + threadIdx.x;
    int n = t >> 5;
    int lane = t & 31;
    if (n >= N_NODES) return;

    const float* es_in = g_es + in_par * N_NODES;
    const float* ed_in = g_ed + in_par * N_NODES;

    int beg = g_rowstart[n], end = g_rowstart[n + 1];
    int deg = end - beg;
    float ed_n = ed_in[n];

    float mx = NEG_INF, sm = 0.0f, acc = 0.0f, inv;

    if (deg <= 64) {
        // -------- light register-cached path (2 blocks, 4 extra regs) --------
        int i0 = beg + lane, i1 = beg + 32 + lane;
        int s0 = 0, s1 = 0;
        float sc0 = NEG_INF, sc1 = NEG_INF;
        if (i0 < end) {
            s0 = g_csr_src[i0];
            sc0 = leaky(es_in[s0] + ed_n);
        }
        if (i1 < end) {
            s1 = g_csr_src[i1];
            sc1 = leaky(es_in[s1] + ed_n);
        }
        mx = fmaxf(sc0, sc1);
#pragma unroll
        for (int off = 16; off > 0; off >>= 1)
            mx = fmaxf(mx, __shfl_xor_sync(FULLMASK, mx, off));
        if (mx == NEG_INF) mx = 0.0f;    // deg==0 guard

        float ev0 = __expf(sc0 - mx);    // inactive lanes -> exp(-inf)=0
        float ev1 = __expf(sc1 - mx);
        sm = ev0 + ev1;
#pragma unroll
        for (int off = 16; off > 0; off >>= 1)
            sm += __shfl_xor_sync(FULLMASK, sm, off);
        inv = 1.0f / (sm + 1e-8f);

        int cnt0 = min(deg, 32);
        if (cnt0 == 32) {
#pragma unroll
            for (int j = 0; j < 32; ++j) {
                float evj = __shfl_sync(FULLMASK, ev0, j);
                int   sj  = __shfl_sync(FULLMASK, s0, j);
                acc += evj * __ldg(&g_transformed[sj * OUT_F + lane]);
            }
        } else {
#pragma unroll 8
            for (int j = 0; j < cnt0; ++j) {
                float evj = __shfl_sync(FULLMASK, ev0, j);
                int   sj  = __shfl_sync(FULLMASK, s0, j);
                acc += evj * __ldg(&g_transformed[sj * OUT_F + lane]);
            }
        }
        int cnt1 = deg - 32;
#pragma unroll 8
        for (int j = 0; j < cnt1; ++j) {
            float evj = __shfl_sync(FULLMASK, ev1, j);
            int   sj  = __shfl_sync(FULLMASK, s1, j);
            acc += evj * __ldg(&g_transformed[sj * OUT_F + lane]);
        }

        if (mode == 1) {
            if (i0 < end) out_alpha[g_csr_eid[i0]] = ev0 * inv;
            if (i1 < end) out_alpha[g_csr_eid[i1]] = ev1 * inv;
        }
    } else {
        // -------- fallback (deg > 64): re-read path --------
        for (int i = beg + lane; i < end; i += 32) {
            int s = g_csr_src[i];
            mx = fmaxf(mx, leaky(es_in[s] + ed_n));
        }
#pragma unroll
        for (int off = 16; off > 0; off >>= 1)
            mx = fmaxf(mx, __shfl_xor_sync(FULLMASK, mx, off));

        for (int base = beg; base < end; base += 32) {
            int i = base + lane;
            int s = 0;
            float ev = 0.0f;
            if (i < end) {
                s = g_csr_src[i];
                ev = __expf(leaky(es_in[s] + ed_n) - mx);
                sm += ev;
            }
            int cnt = min(32, end - base);
#pragma unroll 8
            for (int j = 0; j < cnt; ++j) {
                float evj = __shfl_sync(FULLMASK, ev, j);
                int   sj  = __shfl_sync(FULLMASK, s, j);
                acc += evj * __ldg(&g_transformed[sj * OUT_F + lane]);
            }
        }
#pragma unroll
        for (int off = 16; off > 0; off >>= 1)
            sm += __shfl_xor_sync(FULLMASK, sm, off);
        inv = 1.0f / (sm + 1e-8f);

        if (mode == 1) {
            for (int i = beg + lane; i < end; i += 32) {
                int s = g_csr_src[i];
                float ev = __expf(leaky(es_in[s] + ed_n) - mx);
                out_alpha[g_csr_eid[i]] = ev * inv;
            }
        }
    }

    // -------- fused node update --------
    int idx = n * OUT_F + lane;
    float mh = fmaxf(acc * inv, 0.0f);
    float mu = g_mu[idx];
    float er = mu - mh;

    if (mode == 0) {
        float ps = er * a_vec[lane];
        float pd = er * a_vec[OUT_F + lane];
#pragma unroll
        for (int off = 16; off > 0; off >>= 1) {
            ps += __shfl_xor_sync(FULLMASK, ps, off);
            pd += __shfl_xor_sync(FULLMASK, pd, off);
        }
        if (lane == 0) {
            g_es[out_par * N_NODES + n] = ps;
            g_ed[out_par * N_NODES + n] = pd;
        }
        g_mu[idx] = mu - LR * er;
    } else {
        out_mu[idx]  = mu;
        out_err[idx] = er;
    }
}

// ---------------- launch ----------------
extern "C" void kernel_launch(void* const* d_in, const int* in_sizes, int n_in,
                              void* d_out, int out_size) {
    const float* mu_upper   = (const float*)d_in[0];
    const float* W          = (const float*)d_in[1];
    const float* a_vec      = (const float*)d_in[2];
    const int*   edge_index = (const int*)d_in[3];
    const int*   src = edge_index;
    const int*   dst = edge_index + N_EDGES;

    float* out       = (float*)d_out;
    float* out_mu    = out;
    float* out_err   = out + N_NODES * OUT_F;
    float* out_alpha = out + 2 * N_NODES * OUT_F;

    const int TPB = 256;
    const int nodeBlocks1 = (N_NODES + TPB - 1) / TPB;
    const int edgeBlocks  = (N_EDGES + TPB - 1) / TPB;
    const int warpNodeBlocks = (N_NODES * 32 + TPB - 1) / TPB;

    init_kernel<<<nodeBlocks1, TPB>>>();
    gemm_kernel<<<1024, TPB>>>(mu_upper, W);
    count_kernel<<<edgeBlocks, TPB>>>(dst);
    scanA_kernel<<<SCAN_BLOCKS, SCAN_TPB>>>();
    scanB_kernel<<<1, 64>>>();
    scanC_kernel<<<nodeBlocks1, TPB>>>();
    scatter_kernel<<<edgeBlocks, TPB>>>(src, dst);

    step0_kernel<<<warpNodeBlocks, TPB>>>(a_vec);

    for (int t = 1; t < N_STEPS; ++t) {
        fused_step_kernel<<<warpNodeBlocks, TPB>>>(
            a_vec, (t - 1) & 1, t & 1, 0, nullptr, nullptr, nullptr);
    }
    fused_step_kernel<<<warpNodeBlocks, TPB>>>(
        a_vec, (N_STEPS - 1) & 1, 0, 1, out_mu, out_err, out_alpha);
}

// round 6
// speedup vs baseline: 1.6564x; 1.3709x over previous
#include <cuda_runtime.h>

#define N_NODES 50000
#define N_EDGES 800000
#define IN_F    64
#define OUT_F   32
#define N_STEPS 20
#define LR      0.1f
#define SLOPE   0.2f
#define FULLMASK 0xFFFFFFFFu
#define NEG_INF  __int_as_float(0xFF800000)

#define SCAN_TPB 1024
#define SCAN_BLOCKS ((N_NODES + SCAN_TPB - 1) / SCAN_TPB)   // 49

// ---------------- scratch (device globals; no allocation allowed) ----------------
__device__ float g_transformed[N_NODES * OUT_F];
__device__ float g_mu[N_NODES * OUT_F];
__device__ float g_es[2 * N_NODES];   // double-buffered (parity)
__device__ float g_ed[2 * N_NODES];
__device__ int   g_degi[N_NODES];
__device__ int   g_rowstart[N_NODES + 1];
__device__ int   g_fill[N_NODES];
__device__ int   g_bsum[SCAN_BLOCKS];
__device__ int   g_boff[SCAN_BLOCKS];
__device__ int   g_csr_src[N_EDGES];
__device__ int   g_csr_eid[N_EDGES];

__device__ __forceinline__ float leaky(float x) {
    return (x > 0.0f) ? x : SLOPE * x;
}

// ---------------- setup kernels ----------------

__global__ void init_kernel() {
    int i = blockIdx.x * blockDim.x + threadIdx.x;
    if (i < N_NODES) g_degi[i] = 0;
}

// transformed = mu_upper @ W^T. Warp per node (grid-stride), lane = out feature.
__global__ void gemm_kernel(const float* __restrict__ mu_upper,
                            const float* __restrict__ W) {
    __shared__ float Wt[IN_F][OUT_F];   // Wt[k][f] = W[f*IN_F + k]
    for (int i = threadIdx.x; i < IN_F * OUT_F; i += blockDim.x) {
        int k = i >> 5, f = i & 31;
        Wt[k][f] = W[f * IN_F + k];
    }
    __syncthreads();

    int lane = threadIdx.x & 31;
    int warpsPerGrid = (gridDim.x * blockDim.x) >> 5;
    int w0 = (blockIdx.x * blockDim.x + threadIdx.x) >> 5;

    for (int n = w0; n < N_NODES; n += warpsPerGrid) {
        const float* row = mu_upper + n * IN_F;
        float r0 = row[lane];
        float r1 = row[lane + 32];
        float acc = 0.0f;
#pragma unroll
        for (int k = 0; k < 32; ++k)
            acc = fmaf(__shfl_sync(FULLMASK, r0, k), Wt[k][lane], acc);
#pragma unroll
        for (int k = 0; k < 32; ++k)
            acc = fmaf(__shfl_sync(FULLMASK, r1, k), Wt[32 + k][lane], acc);
        g_transformed[n * OUT_F + lane] = acc;
    }
}

__global__ void count_kernel(const int* __restrict__ dst) {
    int e = blockIdx.x * blockDim.x + threadIdx.x;
    if (e >= N_EDGES) return;
    atomicAdd(&g_degi[dst[e]], 1);
}

__global__ void scanA_kernel() {
    __shared__ int warp_sums[32];
    int tid  = threadIdx.x;
    int lane = tid & 31;
    int wid  = tid >> 5;
    int idx  = blockIdx.x * SCAN_TPB + tid;

    int v = (idx < N_NODES) ? g_degi[idx] : 0;
    int x = v;
#pragma unroll
    for (int off = 1; off < 32; off <<= 1) {
        int y = __shfl_up_sync(FULLMASK, x, off);
        if (lane >= off) x += y;
    }
    if (lane == 31) warp_sums[wid] = x;
    __syncthreads();
    if (wid == 0) {
        int w = warp_sums[lane];
#pragma unroll
        for (int off = 1; off < 32; off <<= 1) {
            int y = __shfl_up_sync(FULLMASK, w, off);
            if (lane >= off) w += y;
        }
        warp_sums[lane] = w;
    }
    __syncthreads();
    int incl = x + ((wid > 0) ? warp_sums[wid - 1] : 0);
    if (idx < N_NODES) g_rowstart[idx] = incl - v;
    if (tid == SCAN_TPB - 1) g_bsum[blockIdx.x] = incl;
}

__global__ void scanB_kernel() {
    __shared__ int s[64];
    int t = threadIdx.x;
    int v = (t < SCAN_BLOCKS) ? g_bsum[t] : 0;
    s[t] = v;
    __syncthreads();
#pragma unroll
    for (int off = 1; off < 64; off <<= 1) {
        int x = (t >= off) ? s[t - off] : 0;
        __syncthreads();
        s[t] += x;
        __syncthreads();
    }
    if (t < SCAN_BLOCKS) g_boff[t] = s[t] - v;
    if (t == 63) g_rowstart[N_NODES] = s[63];
}

__global__ void scanC_kernel() {
    int idx = blockIdx.x * blockDim.x + threadIdx.x;
    if (idx >= N_NODES) return;
    int r = g_rowstart[idx] + g_boff[idx >> 10];
    g_rowstart[idx] = r;
    g_fill[idx] = r;
}

__global__ void scatter_kernel(const int* __restrict__ src,
                               const int* __restrict__ dst) {
    int e = blockIdx.x * blockDim.x + threadIdx.x;
    if (e >= N_EDGES) return;
    int pos = atomicAdd(&g_fill[dst[e]], 1);
    g_csr_src[pos] = src[e];
    g_csr_eid[pos] = e;
}

// ---------------- step 0: uniform-alpha top-down + node update (mu0 = 0) --------
// quarter-warp float4 layout: lane = (q = lane>>3, fl = lane&7)
__global__ void step0_kernel(const float* __restrict__ a_vec) {
    int t = blockIdx.x * blockDim.x + threadIdx.x;
    int n = t >> 5;
    int lane = t & 31;
    if (n >= N_NODES) return;
    int q  = lane >> 3;
    int fl = lane & 7;

    int beg = g_rowstart[n], end = g_rowstart[n + 1];
    int deg = end - beg;

    float4 acc = make_float4(0.f, 0.f, 0.f, 0.f);
    for (int base = 0; base < deg; base += 4) {
        int e = base + q;
        if (e < deg) {
            int s = __ldg(&g_csr_src[beg + e]);
            const float4 r = *(const float4*)(g_transformed + s * OUT_F + fl * 4);
            acc.x += r.x; acc.y += r.y; acc.z += r.z; acc.w += r.w;
        }
    }
    // reduce across quarters
#pragma unroll
    for (int off = 8; off <= 16; off <<= 1) {
        acc.x += __shfl_xor_sync(FULLMASK, acc.x, off);
        acc.y += __shfl_xor_sync(FULLMASK, acc.y, off);
        acc.z += __shfl_xor_sync(FULLMASK, acc.z, off);
        acc.w += __shfl_xor_sync(FULLMASK, acc.w, off);
    }
    float inv = 1.0f / ((float)deg + 1e-8f);
    float4 mh = make_float4(fmaxf(acc.x * inv, 0.f), fmaxf(acc.y * inv, 0.f),
                            fmaxf(acc.z * inv, 0.f), fmaxf(acc.w * inv, 0.f));
    // er = mu0 - mh = -mh
    const float4 as = *(const float4*)(a_vec + fl * 4);
    const float4 ad = *(const float4*)(a_vec + OUT_F + fl * 4);
    float ps = -(mh.x * as.x + mh.y * as.y + mh.z * as.z + mh.w * as.w);
    float pd = -(mh.x * ad.x + mh.y * ad.y + mh.z * ad.z + mh.w * ad.w);
#pragma unroll
    for (int off = 1; off <= 4; off <<= 1) {
        ps += __shfl_xor_sync(FULLMASK, ps, off);
        pd += __shfl_xor_sync(FULLMASK, pd, off);
    }
    if (lane == 0) {
        g_es[n] = ps;
        g_ed[n] = pd;
    }
    if (q == 0) {
        float4 mu1 = make_float4(LR * mh.x, LR * mh.y, LR * mh.z, LR * mh.w);
        *(float4*)(g_mu + n * OUT_F + fl * 4) = mu1;
    }
}

// ---------------- fused step: softmax + aggregate + node update ----------------
// mode 0: intermediate (writes mu, es/ed[out_par]); mode 1: final outputs.
__global__ void __launch_bounds__(256)
fused_step_kernel(const float* __restrict__ a_vec,
                  int in_par, int out_par, int mode,
                  float* __restrict__ out_mu,
                  float* __restrict__ out_err,
                  float* __restrict__ out_alpha) {
    int t = blockIdx.x * blockDim.x + threadIdx.x;
    int n = t >> 5;
    int lane = t & 31;
    if (n >= N_NODES) return;
    int q  = lane >> 3;
    int fl = lane & 7;

    const float* es_in = g_es + in_par * N_NODES;
    const float* ed_in = g_ed + in_par * N_NODES;

    int beg = g_rowstart[n], end = g_rowstart[n + 1];
    int deg = end - beg;
    float ed_n = ed_in[n];

    float inv;
    float4 acc = make_float4(0.f, 0.f, 0.f, 0.f);

    if (deg <= 64) {
        // -------- score phase: lane per edge, 2-block register cache --------
        int i0 = beg + lane, i1 = i0 + 32;
        int s0 = 0, s1 = 0;
        float sc0 = NEG_INF, sc1 = NEG_INF;
        if (i0 < end) {
            s0 = g_csr_src[i0];
            sc0 = leaky(es_in[s0] + ed_n);
        }
        if (i1 < end) {
            s1 = g_csr_src[i1];
            sc1 = leaky(es_in[s1] + ed_n);
        }
        float mx = fmaxf(sc0, sc1);
#pragma unroll
        for (int off = 16; off > 0; off >>= 1)
            mx = fmaxf(mx, __shfl_xor_sync(FULLMASK, mx, off));
        if (mx == NEG_INF) mx = 0.0f;    // deg==0 guard

        float ev0 = __expf(sc0 - mx);    // inactive lanes -> exp(-inf)=0
        float ev1 = __expf(sc1 - mx);
        float sm = ev0 + ev1;
#pragma unroll
        for (int off = 16; off > 0; off >>= 1)
            sm += __shfl_xor_sync(FULLMASK, sm, off);
        inv = 1.0f / (sm + 1e-8f);

        // -------- accumulate: 4 edges/iter, quarter per edge, float4/lane ----
        if (deg <= 32) {
            for (int base = 0; base < deg; base += 4) {
                int e = base + q;
                int   sj  = __shfl_sync(FULLMASK, s0,  e & 31);
                float evj = __shfl_sync(FULLMASK, ev0, e & 31);
                if (e < deg) {
                    const float4 r = *(const float4*)(g_transformed + sj * OUT_F + fl * 4);
                    acc.x = fmaf(evj, r.x, acc.x);
                    acc.y = fmaf(evj, r.y, acc.y);
                    acc.z = fmaf(evj, r.z, acc.z);
                    acc.w = fmaf(evj, r.w, acc.w);
                }
            }
        } else {
            for (int base = 0; base < deg; base += 4) {
                int e = base + q;
                int lsel = e & 31;
                int   sA = __shfl_sync(FULLMASK, s0,  lsel);
                float eA = __shfl_sync(FULLMASK, ev0, lsel);
                int   sB = __shfl_sync(FULLMASK, s1,  lsel);
                float eB = __shfl_sync(FULLMASK, ev1, lsel);
                int   sj  = (e < 32) ? sA : sB;
                float evj = (e < 32) ? eA : eB;
                if (e < deg) {
                    const float4 r = *(const float4*)(g_transformed + sj * OUT_F + fl * 4);
                    acc.x = fmaf(evj, r.x, acc.x);
                    acc.y = fmaf(evj, r.y, acc.y);
                    acc.z = fmaf(evj, r.z, acc.z);
                    acc.w = fmaf(evj, r.w, acc.w);
                }
            }
        }

        if (mode == 1) {
            if (i0 < end) out_alpha[g_csr_eid[i0]] = ev0 * inv;
            if (i1 < end) out_alpha[g_csr_eid[i1]] = ev1 * inv;
        }
    } else {
        // -------- fallback (deg > 64): strided two-pass --------
        float mx = NEG_INF;
        for (int i = beg + lane; i < end; i += 32) {
            int s = g_csr_src[i];
            mx = fmaxf(mx, leaky(es_in[s] + ed_n));
        }
#pragma unroll
        for (int off = 16; off > 0; off >>= 1)
            mx = fmaxf(mx, __shfl_xor_sync(FULLMASK, mx, off));

        float sm = 0.0f;
        for (int base = beg; base < end; base += 32) {
            int i = base + lane;
            int s = 0;
            float ev = 0.0f;
            if (i < end) {
                s = g_csr_src[i];
                ev = __expf(leaky(es_in[s] + ed_n) - mx);
                sm += ev;
            }
            int cnt = min(32, end - base);
            for (int g = 0; g < cnt; g += 4) {
                int e = g + q;
                int   sj  = __shfl_sync(FULLMASK, s,  e & 31);
                float evj = __shfl_sync(FULLMASK, ev, e & 31);
                if (e < cnt) {
                    const float4 r = *(const float4*)(g_transformed + sj * OUT_F + fl * 4);
                    acc.x = fmaf(evj, r.x, acc.x);
                    acc.y = fmaf(evj, r.y, acc.y);
                    acc.z = fmaf(evj, r.z, acc.z);
                    acc.w = fmaf(evj, r.w, acc.w);
                }
            }
        }
#pragma unroll
        for (int off = 16; off > 0; off >>= 1)
            sm += __shfl_xor_sync(FULLMASK, sm, off);
        inv = 1.0f / (sm + 1e-8f);

        if (mode == 1) {
            for (int i = beg + lane; i < end; i += 32) {
                int s = g_csr_src[i];
                float ev = __expf(leaky(es_in[s] + ed_n) - mx);
                out_alpha[g_csr_eid[i]] = ev * inv;
            }
        }
    }

    // -------- reduce acc across quarters (all lanes end with full sums) ------
#pragma unroll
    for (int off = 8; off <= 16; off <<= 1) {
        acc.x += __shfl_xor_sync(FULLMASK, acc.x, off);
        acc.y += __shfl_xor_sync(FULLMASK, acc.y, off);
        acc.z += __shfl_xor_sync(FULLMASK, acc.z, off);
        acc.w += __shfl_xor_sync(FULLMASK, acc.w, off);
    }

    // -------- fused node update (float4 per lane over features fl*4..+3) ----
    int idx4 = n * OUT_F + fl * 4;
    float4 mh = make_float4(fmaxf(acc.x * inv, 0.f), fmaxf(acc.y * inv, 0.f),
                            fmaxf(acc.z * inv, 0.f), fmaxf(acc.w * inv, 0.f));
    float4 mu = *(const float4*)(g_mu + idx4);
    float4 er = make_float4(mu.x - mh.x, mu.y - mh.y, mu.z - mh.z, mu.w - mh.w);

    if (mode == 0) {
        const float4 as = *(const float4*)(a_vec + fl * 4);
        const float4 ad = *(const float4*)(a_vec + OUT_F + fl * 4);
        float ps = er.x * as.x + er.y * as.y + er.z * as.z + er.w * as.w;
        float pd = er.x * ad.x + er.y * ad.y + er.z * ad.z + er.w * ad.w;
#pragma unroll
        for (int off = 1; off <= 4; off <<= 1) {
            ps += __shfl_xor_sync(FULLMASK, ps, off);
            pd += __shfl_xor_sync(FULLMASK, pd, off);
        }
        if (lane == 0) {
            g_es[out_par * N_NODES + n] = ps;
            g_ed[out_par * N_NODES + n] = pd;
        }
        if (q == 0) {
            float4 mun = make_float4(mu.x - LR * er.x, mu.y - LR * er.y,
                                     mu.z - LR * er.z, mu.w - LR * er.w);
            *(float4*)(g_mu + idx4) = mun;
        }
    } else {
        if (q == 0) {
            *(float4*)(out_mu + idx4)  = mu;
            *(float4*)(out_err + idx4) = er;
        }
    }
}

// ---------------- launch ----------------
extern "C" void kernel_launch(void* const* d_in, const int* in_sizes, int n_in,
                              void* d_out, int out_size) {
    const float* mu_upper   = (const float*)d_in[0];
    const float* W          = (const float*)d_in[1];
    const float* a_vec      = (const float*)d_in[2];
    const int*   edge_index = (const int*)d_in[3];
    const int*   src = edge_index;
    const int*   dst = edge_index + N_EDGES;

    float* out       = (float*)d_out;
    float* out_mu    = out;
    float* out_err   = out + N_NODES * OUT_F;
    float* out_alpha = out + 2 * N_NODES * OUT_F;

    const int TPB = 256;
    const int nodeBlocks1 = (N_NODES + TPB - 1) / TPB;
    const int edgeBlocks  = (N_EDGES + TPB - 1) / TPB;
    const int warpNodeBlocks = (N_NODES * 32 + TPB - 1) / TPB;

    init_kernel<<<nodeBlocks1, TPB>>>();
    gemm_kernel<<<1024, TPB>>>(mu_upper, W);
    count_kernel<<<edgeBlocks, TPB>>>(dst);
    scanA_kernel<<<SCAN_BLOCKS, SCAN_TPB>>>();
    scanB_kernel<<<1, 64>>>();
    scanC_kernel<<<nodeBlocks1, TPB>>>();
    scatter_kernel<<<edgeBlocks, TPB>>>(src, dst);

    step0_kernel<<<warpNodeBlocks, TPB>>>(a_vec);

    for (int t = 1; t < N_STEPS; ++t) {
        fused_step_kernel<<<warpNodeBlocks, TPB>>>(
            a_vec, (t - 1) & 1, t & 1, 0, nullptr, nullptr, nullptr);
    }
    fused_step_kernel<<<warpNodeBlocks, TPB>>>(
        a_vec, (N_STEPS - 1) & 1, 0, 1, out_mu, out_err, out_alpha);
}